// round 10
// baseline (speedup 1.0000x reference)
#include <cuda_runtime.h>

#define B_   8
#define T_   2048
#define C_   192
#define TT   32
#define NBX  (T_ / TT)            // 64
#define RAD  10
#define NTAP (RAD + 1)
#define ROWS_U 54                 // TT + 22
#define ROWS_G 34                 // TT + 2
#define NTH  384
#define SMEM_BYTES ((ROWS_U + ROWS_G) * C_ * 4)   // 67,584 B -> 3 CTAs/SM

// ---------------------------------------------------------------------------
// Fused tile body. EDGE=true adds boundary guards (blocks 0 and NBX-1 only).
// Thread = (channel c 0..191, row partition tr 0..1). x streams from global.
// Heat conv done in two low-register passes (center s<=5, wings s=6..10).
// ---------------------------------------------------------------------------
template<bool EDGE>
__device__ __forceinline__ void run_tile(
    const float* __restrict__ xb,
    const float* __restrict__ dw, const float* __restrict__ db,
    const float* __restrict__ lw, const float* __restrict__ lb,
    const float* __restrict__ gamma, const float* __restrict__ beta,
    const float* __restrict__ ow, const float* __restrict__ ob,
    const float* __restrict__ kk,
    float* __restrict__ outb,
    float* us, float* vs, float* s_mu, float* s_rs, int t0)
{
    const int tid  = threadIdx.x;
    const int c    = tid % C_;
    const int tr   = tid / C_;     // 0 or 1
    const int lane = tid & 31, wid = tid >> 5;
    const int c2   = c >> 1;

    // ================= phase A: u build (x from global, sliding windows) ====
    {
        const float dwu0 = dw[c2*3+0], dwu1 = dw[c2*3+1], dwu2 = dw[c2*3+2], dbu = db[c2];
        const float lwu0 = lw[c*3+0],  lwu1 = lw[c*3+1],  lwu2 = lw[c*3+2],  lbu = lb[c];
        const float* xc = xb + c2;

        const int j0 = tr * 27;
        const int tstart = t0 - 11 + j0;

        float x0, x1, x2, x3;
        if (EDGE) {
            x0 = (tstart-2 >= 0 && tstart-2 < T_) ? xc[(size_t)(tstart-2)*C_] : 0.f;
            x1 = (tstart-1 >= 0 && tstart-1 < T_) ? xc[(size_t)(tstart-1)*C_] : 0.f;
            x2 = (tstart   >= 0 && tstart   < T_) ? xc[(size_t)(tstart  )*C_] : 0.f;
            x3 = (tstart+1 >= 0 && tstart+1 < T_) ? xc[(size_t)(tstart+1)*C_] : 0.f;
        } else {
            x0 = xc[(size_t)(tstart-2)*C_];
            x1 = xc[(size_t)(tstart-1)*C_];
            x2 = xc[(size_t)(tstart  )*C_];
            x3 = xc[(size_t)(tstart+1)*C_];
        }
        float hm = dbu + dwu0*x0 + dwu1*x1 + dwu2*x2;   // h(tstart-1)
        float hc = dbu + dwu0*x1 + dwu1*x2 + dwu2*x3;   // h(tstart)
        if (EDGE) {
            if (tstart-1 < 0 || tstart-1 >= T_) hm = 0.f;
            if (tstart   < 0 || tstart   >= T_) hc = 0.f;
        }
        float xa = x2, xb2 = x3;
#pragma unroll
        for (int j = 0; j < 27; j++) {
            const int t = tstart + j;
            float xn;
            if (EDGE) xn = (t+2 >= 0 && t+2 < T_) ? xc[(size_t)(t+2)*C_] : 0.f;
            else      xn = xc[(size_t)(t+2)*C_];
            float hp = dbu + dwu0*xa + dwu1*xb2 + dwu2*xn;  // h(t+1)
            if (EDGE && (t+1 < 0 || t+1 >= T_)) hp = 0.f;
            float uv = lbu + lwu0*hm + lwu1*hc + lwu2*hp;
            if (EDGE && (t < 0 || t >= T_)) uv = 0.f;
            us[(j0+j)*C_ + c] = uv;
            hm = hc; hc = hp; xa = xb2; xb2 = xn;
        }
    }
    __syncthreads();

    // ================= phase B: taps + two-pass heat conv -> vs =============
    {
        // closed-form wrapped Gaussian: F_c(s) = exp(-s^2/(4k)) / (2*sqrt(pi*k))
        float f[NTAP];
        {
            const float kc = kk[c];
            const float amp = 0.5f * rsqrtf(3.14159265358979f * kc);
            const float inv = 0.25f / kc;
#pragma unroll
            for (int s = 0; s < NTAP; s++)
                f[s] = amp * expf(-(float)(s*s) * inv);
        }

        const int i0 = tr * 17;    // output rows [i0, i0+17)
        if (!EDGE) {
            // ---- pass 1: center taps s=0..5, 11-register ring ----
            {
                float w[11];
#pragma unroll
                for (int q = 0; q < 10; q++) w[q] = us[(i0+5+q)*C_ + c];
#pragma unroll
                for (int j = 0; j < 17; j++) {
                    w[(j+10) % 11] = us[(i0+j+15)*C_ + c];
                    float v = f[0] * w[(j+5) % 11];
#pragma unroll
                    for (int s = 1; s <= 5; s++)
                        v += f[s] * (w[(j+5-s) % 11] + w[(j+5+s) % 11]);
                    vs[(i0+j)*C_ + c] = v;
                }
            }
            // ---- pass 2: wing taps s=6..10, two 5-register rings ----
            {
                float wl[5], wr[5];
#pragma unroll
                for (int q = 0; q < 4; q++) {
                    wl[q] = us[(i0+q)*C_ + c];
                    wr[q] = us[(i0+16+q)*C_ + c];
                }
#pragma unroll
                for (int j = 0; j < 17; j++) {
                    wl[(j+4) % 5] = us[(i0+j+4)*C_ + c];
                    wr[(j+4) % 5] = us[(i0+j+20)*C_ + c];
                    float v = vs[(i0+j)*C_ + c];
#pragma unroll
                    for (int s = 6; s <= 10; s++)
                        v += f[s] * (wl[(j+10-s) % 5] + wr[(j+s-6) % 5]);
                    vs[(i0+j)*C_ + c] = v;
                }
            }
        } else {
            const int baseu = t0 - 11;
#pragma unroll
            for (int j = 0; j < 17; j++) {
                const int i = i0 + j, t = t0 - 1 + i;
                float v = f[0] * us[(i+RAD)*C_ + c];
#pragma unroll
                for (int s = 1; s <= RAD; s++) {
                    int tl = t - s; tl = (tl >= 0) ? tl : (-1 - tl);
                    int th = t + s; th = (th < T_) ? th : (2*T_ - 1 - th);
                    v += f[s] * (us[(tl-baseu)*C_ + c] + us[(th-baseu)*C_ + c]);
                }
                vs[i*C_ + c] = v;
            }
        }
    }
    __syncthreads();

    // ================= phase C: LN stats (warp per row) =====================
    for (int r = wid; r < ROWS_G; r += 12) {
        float s1 = 0.f, s2 = 0.f;
#pragma unroll
        for (int q = 0; q < 6; q++) {
            float v = vs[r*C_ + lane + 32*q];
            s1 += v; s2 += v*v;
        }
#pragma unroll
        for (int m = 16; m; m >>= 1) {
            s1 += __shfl_xor_sync(0xffffffffu, s1, m);
            s2 += __shfl_xor_sync(0xffffffffu, s2, m);
        }
        if (lane == 0) {
            float mu  = s1 * (1.0f/C_);
            float var = s2 * (1.0f/C_) - mu*mu;
            s_mu[r] = mu;
            s_rs[r] = rsqrtf(var + 1e-5f);
        }
    }
    __syncthreads();

    // ================= phase D: gate (LN apply + silu(z)), z from global ====
    {
        const int zc2 = 96 + c2;
        const float dwz0 = dw[zc2*3+0], dwz1 = dw[zc2*3+1], dwz2 = dw[zc2*3+2], dbz = db[zc2];
        const float lwz0 = lw[(C_+c)*3+0], lwz1 = lw[(C_+c)*3+1], lwz2 = lw[(C_+c)*3+2], lbz = lb[C_+c];
        const float ga = gamma[c], be = beta[c];
        const float* xz = xb + zc2;

        const int i0 = tr * 17;
        const int tstart = t0 - 1 + i0;

        float x0, x1, x2, x3;
        if (EDGE) {
            x0 = (tstart-2 >= 0 && tstart-2 < T_) ? xz[(size_t)(tstart-2)*C_] : 0.f;
            x1 = (tstart-1 >= 0 && tstart-1 < T_) ? xz[(size_t)(tstart-1)*C_] : 0.f;
            x2 = (tstart   >= 0 && tstart   < T_) ? xz[(size_t)(tstart  )*C_] : 0.f;
            x3 = (tstart+1 >= 0 && tstart+1 < T_) ? xz[(size_t)(tstart+1)*C_] : 0.f;
        } else {
            x0 = xz[(size_t)(tstart-2)*C_];
            x1 = xz[(size_t)(tstart-1)*C_];
            x2 = xz[(size_t)(tstart  )*C_];
            x3 = xz[(size_t)(tstart+1)*C_];
        }
        float hm = dbz + dwz0*x0 + dwz1*x1 + dwz2*x2;
        float hc = dbz + dwz0*x1 + dwz1*x2 + dwz2*x3;
        if (EDGE) {
            if (tstart-1 < 0 || tstart-1 >= T_) hm = 0.f;
            if (tstart   < 0 || tstart   >= T_) hc = 0.f;
        }
        float xa = x2, xb2 = x3;
#pragma unroll
        for (int j = 0; j < 17; j++) {
            const int i = i0 + j, t = tstart + j;
            float xn;
            if (EDGE) xn = (t+2 >= 0 && t+2 < T_) ? xz[(size_t)(t+2)*C_] : 0.f;
            else      xn = xz[(size_t)(t+2)*C_];
            float hp = dbz + dwz0*xa + dwz1*xb2 + dwz2*xn;
            if (EDGE && (t+1 < 0 || t+1 >= T_)) hp = 0.f;
            float zv = lbz + lwz0*hm + lwz1*hc + lwz2*hp;
            hm = hc; hc = hp; xa = xb2; xb2 = xn;

            float v = vs[i*C_ + c];
            float g = (v - s_mu[i]) * s_rs[i] * ga + be;
            g *= zv * (1.0f / (1.0f + __expf(-zv)));
            if (EDGE && (t < 0 || t >= T_)) g = 0.f;
            vs[i*C_ + c] = g;
        }
    }
    __syncthreads();

    // ================= phase E: final conv3 + store =========================
    {
        const float ow0 = ow[c*3+0], ow1 = ow[c*3+1], ow2 = ow[c*3+2], obc = ob[c];
        const int i0 = tr * 16;
        float g0 = vs[(i0+0)*C_ + c];
        float g1 = vs[(i0+1)*C_ + c];
#pragma unroll
        for (int j = 0; j < 16; j++) {
            float g2 = vs[(i0+j+2)*C_ + c];
            outb[(size_t)(t0 + i0 + j)*C_ + c] = obc + ow0*g0 + ow1*g1 + ow2*g2;
            g0 = g1; g1 = g2;
        }
    }
}

// ---------------------------------------------------------------------------
__global__ __launch_bounds__(NTH, 3)
void fused_kernel(const float* __restrict__ x,
                  const float* __restrict__ dw, const float* __restrict__ db,
                  const float* __restrict__ lw, const float* __restrict__ lb,
                  const float* __restrict__ gamma, const float* __restrict__ beta,
                  const float* __restrict__ ow, const float* __restrict__ ob,
                  const float* __restrict__ kk,
                  float* __restrict__ out)
{
    extern __shared__ float sm[];
    float* us = sm;
    float* vs = sm + ROWS_U * C_;
    __shared__ float s_mu[ROWS_G], s_rs[ROWS_G];

    const int b  = blockIdx.y;
    const int bx = blockIdx.x;
    const int t0 = bx * TT;
    const float* xb   = x   + (size_t)b * T_ * C_;
    float*       outb = out + (size_t)b * T_ * C_;

    if (bx == 0 || bx == NBX - 1)
        run_tile<true >(xb, dw, db, lw, lb, gamma, beta, ow, ob, kk, outb,
                        us, vs, s_mu, s_rs, t0);
    else
        run_tile<false>(xb, dw, db, lw, lb, gamma, beta, ow, ob, kk, outb,
                        us, vs, s_mu, s_rs, t0);
}

// ---------------------------------------------------------------------------
extern "C" void kernel_launch(void* const* d_in, const int* in_sizes, int n_in,
                              void* d_out, int out_size)
{
    const float* x  = (const float*)d_in[0];
    const float* dw = (const float*)d_in[1];
    const float* db = (const float*)d_in[2];
    const float* lw = (const float*)d_in[3];
    const float* lb = (const float*)d_in[4];
    const float* ga = (const float*)d_in[5];
    const float* be = (const float*)d_in[6];
    const float* ow = (const float*)d_in[7];
    const float* ob = (const float*)d_in[8];
    const float* k  = (const float*)d_in[9];
    float* out = (float*)d_out;

    cudaFuncSetAttribute(fused_kernel, cudaFuncAttributeMaxDynamicSharedMemorySize,
                         SMEM_BYTES);

    fused_kernel<<<dim3(NBX, B_), NTH, SMEM_BYTES>>>(x, dw, db, lw, lb,
                                                     ga, be, ow, ob, k, out);
}